// round 17
// baseline (speedup 1.0000x reference)
#include <cuda_runtime.h>
#include <cuda_bf16.h>
#include <cuda_fp16.h>
#include <cstdint>
#include <cstring>

// BatchHardLoss round 16: 64x64 warp tiles (R7 layout) + f16 accumulators
// (R11) -> halved LDSM traffic per MAC without register spills.
// CTA 128x256, occ 1, A resident 64KB + 3x32KB B ring. Corr tail + convert +
// finalize unchanged.

#define BATCH 8192
#define DIMK  256
#define NCLS  512
#define GAMMA 0.001f

static __device__ float g_all[BATCH];
static __device__ float g_pos[BATCH];
static __device__ float g_same[BATCH];
static __device__ int   g_cnt[NCLS];
static __device__ int   g_members[NCLS * 16];
static __device__ __nv_bfloat16 g_Xb[BATCH * DIMK];

constexpr int BM = 128;
constexpr int GRID_MAIN = 132;               // 132 x 8 jobs = 1056
constexpr int JOBS_PER_CTA = 8;
constexpr int GRID_ALL = GRID_MAIN + NCLS;
constexpr int AKCHUNK = 16384;               // A: 128 rows x 128B
constexpr int BKCHUNK = 32768;               // B: 256 rows x 128B
constexpr int ATILE = 65536;
constexpr int SMEM_DYN = ATILE + 3 * BKCHUNK;  // 160KB

#define SW128(o) ((o) ^ (((o) >> 3) & 0x70))

__device__ __forceinline__ uint32_t bf2_as_u32(__nv_bfloat162 v) {
    uint32_t r; memcpy(&r, &v, 4); return r;
}
__device__ __forceinline__ __nv_bfloat162 u32_as_bf2(uint32_t v) {
    __nv_bfloat162 r; memcpy(&r, &v, 4); return r;
}
__device__ __forceinline__ __half2 u32_as_h2(uint32_t v) {
    __half2 r; memcpy(&r, &v, 4); return r;
}

__device__ __forceinline__ void cp_async16(uint32_t dst, const void* src) {
    asm volatile("cp.async.cg.shared.global [%0], [%1], 16;\n" :: "r"(dst), "l"(src));
}
#define CP_COMMIT() asm volatile("cp.async.commit_group;\n" ::: "memory")
#define CP_WAIT(N)  asm volatile("cp.async.wait_group %0;\n" :: "n"(N) : "memory")

#define PACK2(d, a, b)    asm("mov.b64 %0, {%1,%2};" : "=l"(d) : "f"(a), "f"(b))
#define UNPACK2(a, b, s)  asm("mov.b64 {%0,%1}, %2;" : "=f"(a), "=f"(b) : "l"(s))
#define MUL2(d, a, b)     asm("mul.rn.f32x2 %0, %1, %2;" : "=l"(d) : "l"(a), "l"(b))
#define ADD2(d, a, b)     asm("add.rn.f32x2 %0, %1, %2;" : "=l"(d) : "l"(a), "l"(b))
#define FMA2(d, a, b, c)  asm("fma.rn.f32x2 %0, %1, %2, %3;" : "=l"(d) : "l"(a), "l"(b), "l"(c))

// ---------------- convert + bucket ----------------

__global__ void bhl_convert_kernel(const float* __restrict__ X,
                                   const int* __restrict__ T,
                                   float* __restrict__ out) {
    int i = blockIdx.x * blockDim.x + threadIdx.x;   // float4 index
    float4 v = ((const float4*)X)[i];
    uint32_t lo = ((uint32_t)__bfloat16_as_ushort(__float2bfloat16_rn(v.y)) << 16)
                |  (uint32_t)__bfloat16_as_ushort(__float2bfloat16_rn(v.x));
    uint32_t hi = ((uint32_t)__bfloat16_as_ushort(__float2bfloat16_rn(v.w)) << 16)
                |  (uint32_t)__bfloat16_as_ushort(__float2bfloat16_rn(v.z));
    ((uint2*)g_Xb)[i] = make_uint2(lo, hi);
    if (i < BATCH) {
        g_all[i] = 0.0f;
        int c = T[i];
        int s = atomicAdd(&g_cnt[c], 1);
        if (s < 16) g_members[c * 16 + s] = i;
    }
    if (i == 0) out[0] = 0.0f;
}

// ---------------- tile loaders ----------------

__device__ __forceinline__ void load_tileA(uint32_t sdst, const char* srcRow0, int tid) {
#pragma unroll
    for (int i = 0; i < 16; i++) {
        int s = i * 256 + tid;
        int row = s >> 5;
        int seg = s & 31;
        int chunk = seg >> 3, w = seg & 7;
        uint32_t soff = chunk * AKCHUNK + SW128(row * 128 + w * 16);
        cp_async16(sdst + soff, srcRow0 + (size_t)row * 512 + seg * 16);
    }
}

// B chunk: 256 rows x 128B (k-chunk kc); rows masked for diagonal singles
__device__ __forceinline__ void load_chunkB(uint32_t sdst, const char* srcRow0,
                                            int kc, int tid, int rowmask) {
#pragma unroll
    for (int i = 0; i < 8; i++) {
        int s = i * 256 + tid;            // 0..2047
        int n = s >> 3, w = s & 7;
        int rr = n & rowmask;
        uint32_t soff = SW128(n * 128 + w * 16);
        cp_async16(sdst + soff, srcRow0 + (size_t)rr * 512 + kc * 128 + w * 16);
    }
}

// ---------------- corr path (tail CTAs) ----------------

__device__ void corr_block(char* dynsmem, const float* __restrict__ X, int c, int tid) {
    uint32_t (*rows)[132] = (uint32_t(*)[132])dynsmem;
    int* sm = (int*)(dynsmem + 16 * 132 * sizeof(uint32_t));
    int K = g_cnt[c];
    if (K > 16) K = 16;
    if (tid < 16) sm[tid] = (tid < K) ? g_members[c * 16 + tid] : 0;
    __syncthreads();
    if (tid == 0) g_cnt[c] = 0;            // self-reset for next graph replay
#pragma unroll
    for (int f = tid; f < 512; f += 256) {
        int row = f >> 5, q = f & 31;
        const float* p = X + (size_t)sm[row] * DIMK + q * 8;
        float4 a = *(const float4*)p;
        float4 b = *(const float4*)(p + 4);
        uint32_t w0 = bf2_as_u32(__floats2bfloat162_rn(a.x, a.y));
        uint32_t w1 = bf2_as_u32(__floats2bfloat162_rn(a.z, a.w));
        uint32_t w2 = bf2_as_u32(__floats2bfloat162_rn(b.x, b.y));
        uint32_t w3 = bf2_as_u32(__floats2bfloat162_rn(b.z, b.w));
        *(uint4*)&rows[row][q * 4] = make_uint4(w0, w1, w2, w3);
    }
    __syncthreads();
    const int i = tid >> 4, j = tid & 15;
    const uint4* ri = (const uint4*)&rows[i][0];
    const uint4* rj = (const uint4*)&rows[j][0];
    float dot = 0.0f;
#pragma unroll
    for (int t = 0; t < 8; t++) {
        uint4 a = ri[t], b = rj[t];
        float2 fa, fb;
        fa = __bfloat1622float2(u32_as_bf2(a.x)); fb = __bfloat1622float2(u32_as_bf2(b.x));
        dot += fa.x * fb.x + fa.y * fb.y;
        fa = __bfloat1622float2(u32_as_bf2(a.y)); fb = __bfloat1622float2(u32_as_bf2(b.y));
        dot += fa.x * fb.x + fa.y * fb.y;
        fa = __bfloat1622float2(u32_as_bf2(a.z)); fb = __bfloat1622float2(u32_as_bf2(b.z));
        dot += fa.x * fb.x + fa.y * fb.y;
        fa = __bfloat1622float2(u32_as_bf2(a.w)); fb = __bfloat1622float2(u32_as_bf2(b.w));
        dot += fa.x * fb.x + fa.y * fb.y;
    }
    float w = fminf(fmaxf(dot * GAMMA, -16.0f), 16.0f);
    const bool valid = (i < K) && (j < K);
    float epos  = (valid && i != j) ? __expf(-w) : 0.0f;
    float esame = valid ? __expf(w) : 0.0f;
#pragma unroll
    for (int o = 8; o; o >>= 1) {
        epos  += __shfl_xor_sync(0xffffffffu, epos, o);
        esame += __shfl_xor_sync(0xffffffffu, esame, o);
    }
    if (j == 0 && i < K) {
        g_pos[sm[i]]  = epos;
        g_same[sm[i]] = esame;
    }
}

// ---------------- main kernel ----------------

__global__ __launch_bounds__(256, 1)
void bhl_main_kernel(const float* __restrict__ X) {
    extern __shared__ char dynsmem[];

    const int tid  = threadIdx.x;
    const int bid  = blockIdx.x;

    if (bid >= GRID_MAIN) {
        corr_block(dynsmem, X, bid - GRID_MAIN, tid);
        return;
    }

    const int lane = tid & 31;
    const int wid  = tid >> 5;
    const int wm   = wid >> 2;            // 0..1 : M half
    const int wn   = wid & 3;             // 0..3 : 64-col slice of 256

    // decode job start
    int I = 0, rem = bid * JOBS_PER_CTA;
    for (;;) { int c = (65 - I) >> 1; if (rem < c) break; rem -= c; I++; }
    int k = rem;

    auto jobJS = [](int I_, int k_, int& J_, bool& s_) {
        int L = 64 - I_;
        if (L & 1) { s_ = (k_ == 0); J_ = s_ ? I_ : I_ + 2 * k_ - 1; }
        else       { s_ = false;     J_ = I_ + 2 * k_; }
    };

    int J; bool sgl;
    jobJS(I, k, J, sgl);

    const uint32_t sb = (uint32_t)__cvta_generic_to_shared(dynsmem);
    const uint32_t aBase = sb;
    const uint32_t bBase = sb + ATILE;

    const char* Xb = (const char*)g_Xb;

    load_tileA(aBase, Xb + (size_t)I * BM * 512, tid);
    load_chunkB(bBase, Xb + (size_t)J * BM * 512, 0, tid, sgl ? 127 : 255);
    CP_COMMIT();
    load_chunkB(bBase + BKCHUNK, Xb + (size_t)J * BM * 512, 1, tid, sgl ? 127 : 255);
    CP_COMMIT();

    uint32_t acc[4][8][2];                     // f16x2 accumulators, 64 regs
#pragma unroll
    for (int a = 0; a < 4; a++)
#pragma unroll
        for (int b = 0; b < 8; b++) { acc[a][b][0] = 0; acc[a][b][1] = 0; }

    unsigned long long G2, P4, P3, P2, P1, P0, ZERO2;
    unsigned long long accR[8], colAcc[8];
    {
        const float g = GAMMA, z = 0.0f;
        PACK2(G2, g, g); PACK2(ZERO2, z, z);
        P4 = P3 = P2 = P1 = P0 = ZERO2;
#pragma unroll
        for (int i = 0; i < 8; i++) { accR[i] = ZERO2; colAcc[i] = ZERO2; }
    }

    int oldI = 0, oldJ = 0;
    bool haveOld = false, oldSingle = false;
    bool reloadedA = false;
    int gchunk = 0;

    auto setPoly = [&](bool s_) {
        float sc = s_ ? 0.5f : 1.0f;
        float p4 = sc * (1.0f / 24.0f), p3 = sc * (1.0f / 6.0f), p2 = sc * 0.5f;
        PACK2(P4, p4, p4); PACK2(P3, p3, p3); PACK2(P2, p2, p2);
        PACK2(P1, sc, sc); PACK2(P0, sc, sc);
    };

    auto epilogue_and_colflush = [&]() {
#pragma unroll
        for (int mt = 0; mt < 4; mt++) {
#pragma unroll
            for (int nt = 0; nt < 8; nt++) {
                unsigned long long d2, w2, e2;
                float2 f0 = __half22float2(u32_as_h2(acc[mt][nt][0]));   // rows-lo
                PACK2(d2, f0.x, f0.y);
                MUL2(w2, d2, G2);
                FMA2(e2, w2, P4, P3);
                FMA2(e2, e2, w2, P2);
                FMA2(e2, e2, w2, P1);
                FMA2(e2, e2, w2, P0);
                ADD2(accR[mt * 2], accR[mt * 2], e2);
                ADD2(colAcc[nt], colAcc[nt], e2);

                float2 f1 = __half22float2(u32_as_h2(acc[mt][nt][1]));   // rows-hi
                PACK2(d2, f1.x, f1.y);
                MUL2(w2, d2, G2);
                FMA2(e2, w2, P4, P3);
                FMA2(e2, e2, w2, P2);
                FMA2(e2, e2, w2, P1);
                FMA2(e2, e2, w2, P0);
                ADD2(accR[mt * 2 + 1], accR[mt * 2 + 1], e2);
                ADD2(colAcc[nt], colAcc[nt], e2);
            }
        }
        const int blkj = oldJ + (wn >> 1);
        const bool doFlush = (!oldSingle) && (blkj != oldI);
#pragma unroll
        for (int nt = 0; nt < 8; nt++) {
            float vlo, vhi;
            UNPACK2(vlo, vhi, colAcc[nt]);
#pragma unroll
            for (int o = 4; o <= 16; o <<= 1) {
                vlo += __shfl_xor_sync(0xffffffffu, vlo, o);
                vhi += __shfl_xor_sync(0xffffffffu, vhi, o);
            }
            if (doFlush && lane < 4) {
                int cb = (wn & 1) * 64 + nt * 8 + 2 * lane;
                atomicAdd(&g_all[blkj * BM + cb], vlo);
                atomicAdd(&g_all[blkj * BM + cb + 1], vhi);
            }
            colAcc[nt] = ZERO2;
        }
    };

    auto rowflush = [&](int Iblk) {
#pragma unroll
        for (int i = 0; i < 8; i++) {
            float vlo, vhi;
            UNPACK2(vlo, vhi, accR[i]);
            float v = vlo + vhi;
            v += __shfl_xor_sync(0xffffffffu, v, 1);
            v += __shfl_xor_sync(0xffffffffu, v, 2);
            if ((lane & 3) == 0) {
                int r = wm * 64 + (i >> 1) * 16 + (lane >> 2) + (i & 1) * 8;
                atomicAdd(&g_all[Iblk * BM + r], v);
            }
            accR[i] = ZERO2;
        }
    };

    for (int pi = 0; pi < JOBS_PER_CTA; ++pi) {
        const bool last = (pi == JOBS_PER_CTA - 1);
        int In = I, kn = k + 1;
        if (kn == ((65 - I) >> 1)) { In = I + 1; kn = 0; }
        int Jn; bool sgln;
        jobJS(In, kn, Jn, sgln);

        const char* Brow  = Xb + (size_t)J  * BM * 512;
        const char* BrowN = Xb + (size_t)Jn * BM * 512;
        const int maskC = sgl ? 127 : 255;
        const int maskN = sgln ? 127 : 255;

        for (int kc = 0; kc < 4; kc++) {
            if (kc == 0 && reloadedA) { CP_WAIT(0); reloadedA = false; }
            else { CP_WAIT(1); }
            __syncthreads();

            if (kc == 0 && haveOld) { epilogue_and_colflush(); haveOld = false; }

            const uint32_t aC = aBase + (uint32_t)kc * AKCHUNK;
            const uint32_t bC = bBase + (uint32_t)(gchunk % 3) * BKCHUNK;

#pragma unroll
            for (int ks = 0; ks < 4; ks++) {
                uint32_t af[4][4];
#pragma unroll
                for (int mt = 0; mt < 4; mt++) {
                    int row = wm * 64 + mt * 16 + (lane & 15);
                    int kseg = ks * 2 + (lane >> 4);
                    uint32_t addr = aC + SW128(row * 128 + kseg * 16);
                    asm volatile("ldmatrix.sync.aligned.m8n8.x4.shared.b16 {%0,%1,%2,%3}, [%4];\n"
                                 : "=r"(af[mt][0]), "=r"(af[mt][1]), "=r"(af[mt][2]), "=r"(af[mt][3])
                                 : "r"(addr));
                }
#pragma unroll
                for (int q = 0; q < 4; q++) {
                    int m = lane >> 3, r = lane & 7;
                    int nIdx = wn * 64 + q * 16 + ((m >> 1) << 3) + r;
                    int kseg = ks * 2 + (m & 1);
                    uint32_t b0, b1, b2, b3;
                    uint32_t addr = bC + SW128(nIdx * 128 + kseg * 16);
                    asm volatile("ldmatrix.sync.aligned.m8n8.x4.shared.b16 {%0,%1,%2,%3}, [%4];\n"
                                 : "=r"(b0), "=r"(b1), "=r"(b2), "=r"(b3) : "r"(addr));
                    if (kc == 0 && ks == 0) {
#pragma unroll
                        for (int mt = 0; mt < 4; mt++) {
                            asm volatile(
                                "mma.sync.aligned.m16n8k16.row.col.f16.f16.f16.f16 "
                                "{%0,%1}, {%2,%3,%4,%5}, {%6,%7}, {%8,%8};\n"
                                : "=r"(acc[mt][2 * q][0]), "=r"(acc[mt][2 * q][1])
                                : "r"(af[mt][0]), "r"(af[mt][1]), "r"(af[mt][2]), "r"(af[mt][3]),
                                  "r"(b0), "r"(b1), "r"(0u));
                            asm volatile(
                                "mma.sync.aligned.m16n8k16.row.col.f16.f16.f16.f16 "
                                "{%0,%1}, {%2,%3,%4,%5}, {%6,%7}, {%8,%8};\n"
                                : "=r"(acc[mt][2 * q + 1][0]), "=r"(acc[mt][2 * q + 1][1])
                                : "r"(af[mt][0]), "r"(af[mt][1]), "r"(af[mt][2]), "r"(af[mt][3]),
                                  "r"(b2), "r"(b3), "r"(0u));
                        }
                    } else {
#pragma unroll
                        for (int mt = 0; mt < 4; mt++) {
                            asm volatile(
                                "mma.sync.aligned.m16n8k16.row.col.f16.f16.f16.f16 "
                                "{%0,%1}, {%2,%3,%4,%5}, {%6,%7}, {%0,%1};\n"
                                : "+r"(acc[mt][2 * q][0]), "+r"(acc[mt][2 * q][1])
                                : "r"(af[mt][0]), "r"(af[mt][1]), "r"(af[mt][2]), "r"(af[mt][3]),
                                  "r"(b0), "r"(b1));
                            asm volatile(
                                "mma.sync.aligned.m16n8k16.row.col.f16.f16.f16.f16 "
                                "{%0,%1}, {%2,%3,%4,%5}, {%6,%7}, {%0,%1};\n"
                                : "+r"(acc[mt][2 * q + 1][0]), "+r"(acc[mt][2 * q + 1][1])
                                : "r"(af[mt][0]), "r"(af[mt][1]), "r"(af[mt][2]), "r"(af[mt][3]),
                                  "r"(b2), "r"(b3));
                        }
                    }
                }
            }

            uint32_t pSlot = bBase + (uint32_t)((gchunk + 2) % 3) * BKCHUNK;
            if (kc < 2) {
                load_chunkB(pSlot, Brow, kc + 2, tid, maskC);
            } else if (!last) {
                load_chunkB(pSlot, BrowN, kc - 2, tid, maskN);
            }
            CP_COMMIT();
            gchunk++;
        }

        oldI = I; oldJ = J; oldSingle = sgl; haveOld = true;
        setPoly(sgl);

        if (last) {
            epilogue_and_colflush(); haveOld = false;
            rowflush(I);
        } else if (In != I) {
            __syncthreads();
            epilogue_and_colflush(); haveOld = false;
            rowflush(I);
            load_tileA(aBase, Xb + (size_t)In * BM * 512, tid);
            CP_COMMIT();
            reloadedA = true;
        }
        I = In; k = kn; J = Jn; sgl = sgln;
    }
}

// ---------------- finalize: 32 x 256, shfl reduce + atomic ----------------

__global__ void bhl_finalize_kernel(float* __restrict__ out) {
    __shared__ float s_red[8];
    const int tid = threadIdx.x;
    const int r = blockIdx.x * 256 + tid;
    float v = __logf(g_pos[r] * (g_all[r] - g_same[r]));
#pragma unroll
    for (int o = 16; o; o >>= 1)
        v += __shfl_xor_sync(0xffffffffu, v, o);
    if ((tid & 31) == 0) s_red[tid >> 5] = v;
    __syncthreads();
    if (tid < 32) {
        float t = (tid < 8) ? s_red[tid] : 0.0f;
#pragma unroll
        for (int o = 4; o; o >>= 1)
            t += __shfl_xor_sync(0xffffffffu, t, o);
        if (tid == 0) atomicAdd(out, t * (1.0f / (float)BATCH));
    }
}

extern "C" void kernel_launch(void* const* d_in, const int* in_sizes, int n_in,
                              void* d_out, int out_size) {
    const float* X = (const float*)d_in[0];
    const int*   T = (const int*)d_in[1];
    float* out = (float*)d_out;

    cudaFuncSetAttribute(bhl_main_kernel, cudaFuncAttributeMaxDynamicSharedMemorySize, SMEM_DYN);

    bhl_convert_kernel<<<(BATCH * DIMK / 4) / 256, 256>>>(X, T, out);
    bhl_main_kernel<<<GRID_ALL, 256, SMEM_DYN>>>(X);
    bhl_finalize_kernel<<<BATCH / 256, 256>>>(out);
}